// round 1
// baseline (speedup 1.0000x reference)
#include <cuda_runtime.h>
#include <cuda_bf16.h>
#include <math.h>

// Problem constants
#define NXD 320
#define GD  640            // OS*NX
#define NCOIL 8
#define NFRAME 8
#define MS 65536
#define NPIX (NXD*NXD)     // 102400

// Scratch (allocations are forbidden -> __device__ globals)
__device__ float2 d_grid[NFRAME*NCOIL*GD*GD];       // 64 x 640 x 640   (~210 MB)
__device__ float2 d_tmp1[NFRAME*NCOIL*GD*NXD];      // 64 x 640 x 320   (~105 MB)
__device__ float2 d_imcrop[NFRAME*NCOIL*NPIX];      // 64 x 320 x 320   (~52 MB)
__device__ float2 d_imt[NFRAME*NPIX];               // 8 x 320 x 320

// ---------------- complex helpers ----------------
__device__ __forceinline__ float2 c_add(float2 a, float2 b){ return make_float2(a.x+b.x, a.y+b.y); }
__device__ __forceinline__ float2 c_sub(float2 a, float2 b){ return make_float2(a.x-b.x, a.y-b.y); }
__device__ __forceinline__ float2 c_mul(float2 a, float2 b){ return make_float2(a.x*b.x - a.y*b.y, a.x*b.y + a.y*b.x); }

// ---------------- 640-point inverse DFT (sign +, unnormalized) ----------------
// Mixed-radix Stockham DIF: radix-5 then 7x radix-2. 320 threads. Result returned
// in whichever shared buffer holds the final data (natural order).
__device__ float2* ifft640_shared(float2* A, float2* B, int tid)
{
    float2* src = A;
    float2* dst = B;

    // ---- stage 1: radix-5, n=640, s=1, m=128 ----
    if (tid < 128) {
        int p = tid;
        float2 a0 = src[p];
        float2 a1 = src[p+128];
        float2 a2 = src[p+256];
        float2 a3 = src[p+384];
        float2 a4 = src[p+512];
        const float C1 =  0.3090169943749474241f;   // cos(2pi/5)
        const float S1 =  0.9510565162951535721f;   // sin(2pi/5)
        const float C2 = -0.8090169943749474241f;   // cos(4pi/5)
        const float S2 =  0.5877852522924731292f;   // sin(4pi/5)
        float2 t1 = c_add(a1,a4), t2 = c_sub(a1,a4);
        float2 t3 = c_add(a2,a3), t4 = c_sub(a2,a3);
        float2 b0 = c_add(a0, c_add(t1,t3));
        float2 m1 = make_float2(a0.x + C1*t1.x + C2*t3.x, a0.y + C1*t1.y + C2*t3.y);
        float2 m2 = make_float2(a0.x + C2*t1.x + C1*t3.x, a0.y + C2*t1.y + C1*t3.y);
        float2 n1 = make_float2(S1*t2.x + S2*t4.x, S1*t2.y + S2*t4.y);
        float2 n2 = make_float2(S2*t2.x - S1*t4.x, S2*t2.y - S1*t4.y);
        // sign +: b_v = m +/- i*n
        float2 b1 = make_float2(m1.x - n1.y, m1.y + n1.x);
        float2 b4 = make_float2(m1.x + n1.y, m1.y - n1.x);
        float2 b2 = make_float2(m2.x - n2.y, m2.y + n2.x);
        float2 b3 = make_float2(m2.x + n2.y, m2.y - n2.x);
        // twiddles exp(+i*2pi*p*v/640)
        float base = 6.283185307179586477f * (float)p * (1.0f/640.0f);
        float s1w,c1w,s2w,c2w,s3w,c3w,s4w,c4w;
        __sincosf(0.0f,&s1w,&c1w); // placeholder to keep compiler calm (unused)
        sincosf(base,        &s1w,&c1w);
        sincosf(2.0f*base,   &s2w,&c2w);
        sincosf(3.0f*base,   &s3w,&c3w);
        sincosf(4.0f*base,   &s4w,&c4w);
        dst[5*p+0] = b0;
        dst[5*p+1] = c_mul(b1, make_float2(c1w,s1w));
        dst[5*p+2] = c_mul(b2, make_float2(c2w,s2w));
        dst[5*p+3] = c_mul(b3, make_float2(c3w,s3w));
        dst[5*p+4] = c_mul(b4, make_float2(c4w,s4w));
    }
    __syncthreads();
    { float2* t = src; src = dst; dst = t; }

    // ---- stages 2..8: radix-2, (n,s) = (128,5) -> (2,320) ----
    #pragma unroll
    for (int n = 128, s = 5; n >= 2; n >>= 1, s <<= 1) {
        int q = tid - (tid / s) * s;
        int p = tid / s;
        float2 a0 = src[tid];
        float2 a1 = src[tid + 320];
        float2 b0 = c_add(a0, a1);
        float2 b1 = c_sub(a0, a1);
        float ang = 6.283185307179586477f * (float)p / (float)n;
        float sn, cs;
        sincosf(ang, &sn, &cs);
        int w0 = 2*tid - q;
        dst[w0]     = b0;
        dst[w0 + s] = c_mul(b1, make_float2(cs, sn));
        __syncthreads();
        float2* t = src; src = dst; dst = t;
    }
    return src;   // final data (8 stages total)
}

// ---------------- kernels ----------------
__global__ void k_zero_grid()
{
    // 64*640*640 float2 = 13107200 float4
    unsigned i = blockIdx.x * blockDim.x + threadIdx.x;
    const unsigned n = (unsigned)(NFRAME*NCOIL) * GD * GD / 2;   // float4 count
    if (i < n) reinterpret_cast<float4*>(d_grid)[i] = make_float4(0.f,0.f,0.f,0.f);
}

__global__ void k_scatter(const float* __restrict__ ksr, const float* __restrict__ ksi,
                          const float* __restrict__ traj, const float* __restrict__ dcf)
{
    int idx = blockIdx.x * blockDim.x + threadIdx.x;   // t*MS + m
    if (idx >= NFRAME * MS) return;
    int t = idx >> 16;
    int m = idx & (MS - 1);

    float u = (traj[m*2*NFRAME + 0*NFRAME + t] + 0.5f) * (float)GD;
    float v = (traj[m*2*NFRAME + 1*NFRAME + t] + 0.5f) * (float)GD;
    float w = dcf[m*NFRAME + t];

    float u0f = floorf(u), v0f = floorf(v);
    float du = u - u0f, dv = v - v0f;
    int i0 = (int)u0f; if (i0 >= GD) i0 -= GD;
    int j0 = (int)v0f; if (j0 >= GD) j0 -= GD;
    int i1 = i0 + 1; if (i1 >= GD) i1 -= GD;
    int j1 = j0 + 1; if (j1 >= GD) j1 -= GD;

    float w00 = (1.0f-du)*(1.0f-dv)*w;
    float w10 = du*(1.0f-dv)*w;
    float w01 = (1.0f-du)*dv*w;
    float w11 = du*dv*w;

    int o00 = i0*GD + j0, o10 = i1*GD + j0, o01 = i0*GD + j1, o11 = i1*GD + j1;

    #pragma unroll
    for (int c = 0; c < NCOIL; c++) {
        float kr = ksr[c*MS + m];
        float ki = ksi[c*MS + m];
        float2* g = d_grid + (size_t)(t*NCOIL + c) * GD * GD;
        atomicAdd(&g[o00].x, kr*w00); atomicAdd(&g[o00].y, ki*w00);
        atomicAdd(&g[o10].x, kr*w10); atomicAdd(&g[o10].y, ki*w10);
        atomicAdd(&g[o01].x, kr*w01); atomicAdd(&g[o01].y, ki*w01);
        atomicAdd(&g[o11].x, kr*w11); atomicAdd(&g[o11].y, ki*w11);
    }
}

// Pass 1: for each (image, row): ifft along columns with input ifftshift,
// output fftshift + crop to 320 columns.
__global__ void k_fft_pass1()
{
    __shared__ float2 A[GD];
    __shared__ float2 B[GD];
    int img = blockIdx.x / GD;
    int r   = blockIdx.x - img * GD;
    int tid = threadIdx.x;   // 0..319

    const float2* row = d_grid + ((size_t)img * GD + r) * GD;
    // ifftshift along columns: x[n] = row[(n+320)%640]
    A[tid]       = row[tid + 320];
    A[tid + 320] = row[tid];
    __syncthreads();

    float2* res = ifft640_shared(A, B, tid);

    // keep columns q in [160,480): stored at j = q-160, value = X[(q+320)%640]
    int j = tid;
    int k = (j < 160) ? (j + 480) : (j - 160);
    d_tmp1[((size_t)img * GD + r) * NXD + j] = res[k];
}

// Pass 2: for each (image, kept column j): ifft along rows with input ifftshift,
// output fftshift + crop to 320 rows; apply 1/(G*G) and deapodization.
__global__ void k_fft_pass2()
{
    __shared__ float2 A[GD];
    __shared__ float2 B[GD];
    int img = blockIdx.x / NXD;
    int j   = blockIdx.x - img * NXD;
    int tid = threadIdx.x;   // 0..319

    A[tid]       = d_tmp1[((size_t)img * GD + (tid + 320)) * NXD + j];
    A[tid + 320] = d_tmp1[((size_t)img * GD + tid) * NXD + j];
    __syncthreads();

    float2* res = ifft640_shared(A, B, tid);

    int i = tid;
    int k = (i < 160) ? (i + 480) : (i - 160);
    float2 v = res[k];

    // deapodization: d[i] = sinc((i-160)/640)^2
    float xi = (float)(i - 160) * (1.0f/640.0f);
    float xj = (float)(j - 160) * (1.0f/640.0f);
    float di, dj;
    if (i == 160) { di = 1.0f; } else { float px = 3.14159265358979324f * xi; float s = sinf(px)/px; di = s*s; }
    if (j == 160) { dj = 1.0f; } else { float px = 3.14159265358979324f * xj; float s = sinf(px)/px; dj = s*s; }
    float scale = 1.0f / (409600.0f * di * dj);
    v.x *= scale; v.y *= scale;

    d_imcrop[(size_t)img * NPIX + i * NXD + j] = v;
}

// Coil combine: imt[t][pix] = sum_c conj(csm[c]) * im[t][c]
__global__ void k_combine(const float* __restrict__ csr, const float* __restrict__ csi)
{
    int idx = blockIdx.x * blockDim.x + threadIdx.x;   // t*NPIX + pix
    if (idx >= NFRAME * NPIX) return;
    int t = idx / NPIX;
    int pix = idx - t * NPIX;
    float re = 0.f, im = 0.f;
    #pragma unroll
    for (int c = 0; c < NCOIL; c++) {
        float2 v = d_imcrop[(size_t)(t*NCOIL + c) * NPIX + pix];
        float cr = csr[c*NPIX + pix];
        float ci = csi[c*NPIX + pix];
        re += cr*v.x + ci*v.y;     // (cr - i*ci)*(vx + i*vy)
        im += cr*v.y - ci*v.x;
    }
    d_imt[idx] = make_float2(re, im);
}

// Motion warp each frame and sum over frames.
__global__ void k_warp_sum(const float* __restrict__ motions, float* __restrict__ out)
{
    int idx = blockIdx.x * blockDim.x + threadIdx.x;   // x*NXD + y
    if (idx >= NPIX) return;
    int x = idx / NXD;
    int y = idx - x * NXD;

    float accr = 0.f, acci = 0.f;
    #pragma unroll
    for (int t = 0; t < NFRAME; t++) {
        float fx = (float)x + motions[(idx*2 + 0)*NFRAME + t];
        float fy = (float)y + motions[(idx*2 + 1)*NFRAME + t];
        fx = fminf(fmaxf(fx, 0.0f), (float)(NXD-1));
        fy = fminf(fmaxf(fy, 0.0f), (float)(NXD-1));
        int x0 = (int)floorf(fx);
        int y0 = (int)floorf(fy);
        int x1 = min(x0 + 1, NXD-1);
        int y1 = min(y0 + 1, NXD-1);
        float dx = fx - (float)x0;
        float dy = fy - (float)y0;
        const float2* im = d_imt + (size_t)t * NPIX;
        float2 v00 = im[x0*NXD + y0];
        float2 v10 = im[x1*NXD + y0];
        float2 v01 = im[x0*NXD + y1];
        float2 v11 = im[x1*NXD + y1];
        float w00 = (1.f-dx)*(1.f-dy), w10 = dx*(1.f-dy), w01 = (1.f-dx)*dy, w11 = dx*dy;
        accr += w00*v00.x + w10*v10.x + w01*v01.x + w11*v11.x;
        acci += w00*v00.y + w10*v10.y + w01*v01.y + w11*v11.y;
    }
    out[idx*2 + 0] = accr;
    out[idx*2 + 1] = acci;
}

// ---------------- launch ----------------
extern "C" void kernel_launch(void* const* d_in, const int* in_sizes, int n_in,
                              void* d_out, int out_size)
{
    const float* ksr     = (const float*)d_in[0];
    const float* ksi     = (const float*)d_in[1];
    const float* traj    = (const float*)d_in[2];
    const float* csr     = (const float*)d_in[3];
    const float* csi     = (const float*)d_in[4];
    const float* dcf     = (const float*)d_in[5];
    const float* motions = (const float*)d_in[6];
    float* out = (float*)d_out;

    const int nzero = NFRAME*NCOIL*GD*GD/2;                 // float4 elements
    k_zero_grid<<<(nzero + 255)/256, 256>>>();
    k_scatter<<<(NFRAME*MS + 255)/256, 256>>>(ksr, ksi, traj, dcf);
    k_fft_pass1<<<NFRAME*NCOIL*GD, NXD>>>();
    k_fft_pass2<<<NFRAME*NCOIL*NXD, NXD>>>();
    k_combine<<<(NFRAME*NPIX + 255)/256, 256>>>(csr, csi);
    k_warp_sum<<<(NPIX + 255)/256, 256>>>(motions, out);
}

// round 2
// speedup vs baseline: 1.2115x; 1.2115x over previous
#include <cuda_runtime.h>
#include <cuda_bf16.h>
#include <math.h>

// Problem constants
#define NXD 320
#define GD  640            // OS*NX
#define NCOIL 8
#define NFRAME 8
#define MS 65536
#define NPIX (NXD*NXD)     // 102400
#define P2B 8              // columns batched per pass-2 block

// Scratch (allocations are forbidden -> __device__ globals)
__device__ float2 d_grid[NFRAME*NCOIL*GD*GD];       // 64 x 640 x 640   (~210 MB)
__device__ float2 d_tmp1[NFRAME*NCOIL*GD*NXD];      // 64 x 640 x 320   (~105 MB)
__device__ float2 d_imcrop[NFRAME*NCOIL*NPIX];      // 64 x 320 x 320   (~52 MB)
__device__ float2 d_imt[NFRAME*NPIX];               // 8 x 320 x 320

// ---------------- complex helpers ----------------
__device__ __forceinline__ float2 c_add(float2 a, float2 b){ return make_float2(a.x+b.x, a.y+b.y); }
__device__ __forceinline__ float2 c_sub(float2 a, float2 b){ return make_float2(a.x-b.x, a.y-b.y); }
__device__ __forceinline__ float2 c_mul(float2 a, float2 b){ return make_float2(a.x*b.x - a.y*b.y, a.x*b.y + a.y*b.x); }

// ---------------- 640-point inverse DFT (sign +, unnormalized) ----------------
// Mixed-radix Stockham DIF: radix-5 then 7x radix-2. 320 threads. After 8 stages
// (even number of swaps) the result is back in A, natural order.
__device__ __forceinline__ void ifft640_shared(float2* A, float2* B, int tid)
{
    float2* src = A;
    float2* dst = B;

    // ---- stage 1: radix-5, n=640, s=1, m=128 ----
    if (tid < 128) {
        int p = tid;
        float2 a0 = src[p];
        float2 a1 = src[p+128];
        float2 a2 = src[p+256];
        float2 a3 = src[p+384];
        float2 a4 = src[p+512];
        const float C1 =  0.3090169943749474241f;   // cos(2pi/5)
        const float S1 =  0.9510565162951535721f;   // sin(2pi/5)
        const float C2 = -0.8090169943749474241f;   // cos(4pi/5)
        const float S2 =  0.5877852522924731292f;   // sin(4pi/5)
        float2 t1 = c_add(a1,a4), t2 = c_sub(a1,a4);
        float2 t3 = c_add(a2,a3), t4 = c_sub(a2,a3);
        float2 b0 = c_add(a0, c_add(t1,t3));
        float2 m1 = make_float2(a0.x + C1*t1.x + C2*t3.x, a0.y + C1*t1.y + C2*t3.y);
        float2 m2 = make_float2(a0.x + C2*t1.x + C1*t3.x, a0.y + C2*t1.y + C1*t3.y);
        float2 n1 = make_float2(S1*t2.x + S2*t4.x, S1*t2.y + S2*t4.y);
        float2 n2 = make_float2(S2*t2.x - S1*t4.x, S2*t2.y - S1*t4.y);
        // sign +: b_v = m +/- i*n
        float2 b1 = make_float2(m1.x - n1.y, m1.y + n1.x);
        float2 b4 = make_float2(m1.x + n1.y, m1.y - n1.x);
        float2 b2 = make_float2(m2.x - n2.y, m2.y + n2.x);
        float2 b3 = make_float2(m2.x + n2.y, m2.y - n2.x);
        // twiddles exp(+i*2pi*p*v/640)
        float base = 6.283185307179586477f * (float)p * (1.0f/640.0f);
        float s1w,c1w,s2w,c2w,s3w,c3w,s4w,c4w;
        __sincosf(base,        &s1w,&c1w);
        __sincosf(2.0f*base,   &s2w,&c2w);
        __sincosf(3.0f*base,   &s3w,&c3w);
        __sincosf(4.0f*base,   &s4w,&c4w);
        dst[5*p+0] = b0;
        dst[5*p+1] = c_mul(b1, make_float2(c1w,s1w));
        dst[5*p+2] = c_mul(b2, make_float2(c2w,s2w));
        dst[5*p+3] = c_mul(b3, make_float2(c3w,s3w));
        dst[5*p+4] = c_mul(b4, make_float2(c4w,s4w));
    }
    __syncthreads();
    { float2* t = src; src = dst; dst = t; }

    // ---- stages 2..8: radix-2, (n,s) = (128,5) -> (2,320) ----
    #pragma unroll
    for (int n = 128, s = 5; n >= 2; n >>= 1, s <<= 1) {
        int q = tid - (tid / s) * s;
        int p = tid / s;
        float2 a0 = src[tid];
        float2 a1 = src[tid + 320];
        float2 b0 = c_add(a0, a1);
        float2 b1 = c_sub(a0, a1);
        float ang = 6.283185307179586477f * (float)p / (float)n;
        float sn, cs;
        __sincosf(ang, &sn, &cs);
        int w0 = 2*tid - q;
        dst[w0]     = b0;
        dst[w0 + s] = c_mul(b1, make_float2(cs, sn));
        __syncthreads();
        float2* t = src; src = dst; dst = t;
    }
}

// ---------------- kernels ----------------
__global__ void k_zero_grid()
{
    unsigned i = blockIdx.x * blockDim.x + threadIdx.x;
    const unsigned n = (unsigned)(NFRAME*NCOIL) * GD * GD / 2;   // float4 count
    if (i < n) reinterpret_cast<float4*>(d_grid)[i] = make_float4(0.f,0.f,0.f,0.f);
}

__global__ void k_scatter(const float* __restrict__ ksr, const float* __restrict__ ksi,
                          const float* __restrict__ traj, const float* __restrict__ dcf)
{
    int idx = blockIdx.x * blockDim.x + threadIdx.x;   // t*MS + m
    if (idx >= NFRAME * MS) return;
    int t = idx >> 16;
    int m = idx & (MS - 1);

    float u = (traj[m*2*NFRAME + 0*NFRAME + t] + 0.5f) * (float)GD;
    float v = (traj[m*2*NFRAME + 1*NFRAME + t] + 0.5f) * (float)GD;
    float w = dcf[m*NFRAME + t];

    float u0f = floorf(u), v0f = floorf(v);
    float du = u - u0f, dv = v - v0f;
    int i0 = (int)u0f; if (i0 >= GD) i0 -= GD;
    int j0 = (int)v0f; if (j0 >= GD) j0 -= GD;
    int i1 = i0 + 1; if (i1 >= GD) i1 -= GD;
    int j1 = j0 + 1; if (j1 >= GD) j1 -= GD;

    float w00 = (1.0f-du)*(1.0f-dv)*w;
    float w10 = du*(1.0f-dv)*w;
    float w01 = (1.0f-du)*dv*w;
    float w11 = du*dv*w;

    int o00 = i0*GD + j0, o10 = i1*GD + j0, o01 = i0*GD + j1, o11 = i1*GD + j1;

    #pragma unroll
    for (int c = 0; c < NCOIL; c++) {
        float kr = ksr[c*MS + m];
        float ki = ksi[c*MS + m];
        float2* g = d_grid + (size_t)(t*NCOIL + c) * GD * GD;
        atomicAdd(&g[o00].x, kr*w00); atomicAdd(&g[o00].y, ki*w00);
        atomicAdd(&g[o10].x, kr*w10); atomicAdd(&g[o10].y, ki*w10);
        atomicAdd(&g[o01].x, kr*w01); atomicAdd(&g[o01].y, ki*w01);
        atomicAdd(&g[o11].x, kr*w11); atomicAdd(&g[o11].y, ki*w11);
    }
}

// Pass 1: for each (image, row): ifft along columns with input ifftshift,
// output fftshift + crop to 320 columns. Global loads/stores coalesced.
__global__ void k_fft_pass1()
{
    __shared__ float2 A[GD];
    __shared__ float2 B[GD];
    int img = blockIdx.x / GD;
    int r   = blockIdx.x - img * GD;
    int tid = threadIdx.x;   // 0..319

    const float2* row = d_grid + ((size_t)img * GD + r) * GD;
    // ifftshift along columns: x[n] = row[(n+320)%640]
    A[tid]       = row[tid + 320];
    A[tid + 320] = row[tid];
    __syncthreads();

    ifft640_shared(A, B, tid);

    // keep columns q in [160,480): stored at j = q-160, value = X[(q+320)%640]
    int j = tid;
    int k = (j < 160) ? (j + 480) : (j - 160);
    d_tmp1[((size_t)img * GD + r) * NXD + j] = A[k];
}

// Pass 2: batched over P2B=8 columns per block. Tile load/store are coalesced
// (column index fastest -> 64B contiguous chunks). 8 sequential 640-pt FFTs
// out of shared column buffers, then crop + deapodize + 1/(G*G).
__global__ void k_fft_pass2()
{
    __shared__ float2 colA[P2B][GD];   // 40 KB
    __shared__ float2 B[GD];           // 5 KB ping buffer (reused per column)
    int img = blockIdx.x / (NXD/P2B);
    int jb  = (blockIdx.x - img * (NXD/P2B)) * P2B;
    int tid = threadIdx.x;   // 0..319

    // Coalesced tile load with input ifftshift folded into the shared index.
    const float2* base = d_tmp1 + (size_t)img * GD * NXD + jb;
    #pragma unroll
    for (int it = 0; it < (GD*P2B)/NXD; it++) {
        int idx = it * NXD + tid;
        int r = idx >> 3;          // 0..639
        int c = idx & (P2B-1);     // 0..7
        int rr = (r < NXD) ? (r + NXD) : (r - NXD);   // ifftshift
        colA[c][rr] = base[(size_t)r * NXD + c];
    }
    __syncthreads();

    #pragma unroll 1
    for (int c = 0; c < P2B; c++) {
        ifft640_shared(colA[c], B, tid);
        // loop ends with __syncthreads() inside the last stage
    }

    // Coalesced tile store: crop + fftshift + deapodization.
    #pragma unroll
    for (int it = 0; it < (NXD*P2B)/NXD; it++) {
        int idx = it * NXD + tid;
        int i = idx >> 3;
        int c = idx & (P2B-1);
        int k = (i < 160) ? (i + 480) : (i - 160);
        float2 v = colA[c][k];

        int j = jb + c;
        float xi = (float)(i - 160) * (1.0f/640.0f);
        float xj = (float)(j - 160) * (1.0f/640.0f);
        float di, dj;
        if (i == 160) { di = 1.0f; } else { float px = 3.14159265358979324f * xi; float s = __sinf(px)/px; di = s*s; }
        if (j == 160) { dj = 1.0f; } else { float px = 3.14159265358979324f * xj; float s = __sinf(px)/px; dj = s*s; }
        float scale = 1.0f / (409600.0f * di * dj);
        v.x *= scale; v.y *= scale;

        d_imcrop[(size_t)img * NPIX + (size_t)i * NXD + j] = v;
    }
}

// Coil combine: imt[t][pix] = sum_c conj(csm[c]) * im[t][c]
__global__ void k_combine(const float* __restrict__ csr, const float* __restrict__ csi)
{
    int idx = blockIdx.x * blockDim.x + threadIdx.x;   // t*NPIX + pix
    if (idx >= NFRAME * NPIX) return;
    int t = idx / NPIX;
    int pix = idx - t * NPIX;
    float re = 0.f, im = 0.f;
    #pragma unroll
    for (int c = 0; c < NCOIL; c++) {
        float2 v = d_imcrop[(size_t)(t*NCOIL + c) * NPIX + pix];
        float cr = csr[c*NPIX + pix];
        float ci = csi[c*NPIX + pix];
        re += cr*v.x + ci*v.y;     // (cr - i*ci)*(vx + i*vy)
        im += cr*v.y - ci*v.x;
    }
    d_imt[idx] = make_float2(re, im);
}

// Motion warp each frame and sum over frames.
__global__ void k_warp_sum(const float* __restrict__ motions, float* __restrict__ out)
{
    int idx = blockIdx.x * blockDim.x + threadIdx.x;   // x*NXD + y
    if (idx >= NPIX) return;
    int x = idx / NXD;
    int y = idx - x * NXD;

    float accr = 0.f, acci = 0.f;
    #pragma unroll
    for (int t = 0; t < NFRAME; t++) {
        float fx = (float)x + motions[(idx*2 + 0)*NFRAME + t];
        float fy = (float)y + motions[(idx*2 + 1)*NFRAME + t];
        fx = fminf(fmaxf(fx, 0.0f), (float)(NXD-1));
        fy = fminf(fmaxf(fy, 0.0f), (float)(NXD-1));
        int x0 = (int)floorf(fx);
        int y0 = (int)floorf(fy);
        int x1 = min(x0 + 1, NXD-1);
        int y1 = min(y0 + 1, NXD-1);
        float dx = fx - (float)x0;
        float dy = fy - (float)y0;
        const float2* im = d_imt + (size_t)t * NPIX;
        float2 v00 = im[x0*NXD + y0];
        float2 v10 = im[x1*NXD + y0];
        float2 v01 = im[x0*NXD + y1];
        float2 v11 = im[x1*NXD + y1];
        float w00 = (1.f-dx)*(1.f-dy), w10 = dx*(1.f-dy), w01 = (1.f-dx)*dy, w11 = dx*dy;
        accr += w00*v00.x + w10*v10.x + w01*v01.x + w11*v11.x;
        acci += w00*v00.y + w10*v10.y + w01*v01.y + w11*v11.y;
    }
    out[idx*2 + 0] = accr;
    out[idx*2 + 1] = acci;
}

// ---------------- launch ----------------
extern "C" void kernel_launch(void* const* d_in, const int* in_sizes, int n_in,
                              void* d_out, int out_size)
{
    const float* ksr     = (const float*)d_in[0];
    const float* ksi     = (const float*)d_in[1];
    const float* traj    = (const float*)d_in[2];
    const float* csr     = (const float*)d_in[3];
    const float* csi     = (const float*)d_in[4];
    const float* dcf     = (const float*)d_in[5];
    const float* motions = (const float*)d_in[6];
    float* out = (float*)d_out;

    const int nzero = NFRAME*NCOIL*GD*GD/2;                 // float4 elements
    k_zero_grid<<<(nzero + 255)/256, 256>>>();
    k_scatter<<<(NFRAME*MS + 255)/256, 256>>>(ksr, ksi, traj, dcf);
    k_fft_pass1<<<NFRAME*NCOIL*GD, NXD>>>();
    k_fft_pass2<<<NFRAME*NCOIL*(NXD/P2B), NXD>>>();
    k_combine<<<(NFRAME*NPIX + 255)/256, 256>>>(csr, csi);
    k_warp_sum<<<(NPIX + 255)/256, 256>>>(motions, out);
}

// round 3
// speedup vs baseline: 1.5357x; 1.2675x over previous
#include <cuda_runtime.h>
#include <cuda_bf16.h>
#include <math.h>

// Problem constants
#define NXD 320
#define GD  640            // OS*NX
#define NCOIL 8
#define NFRAME 8
#define MS 65536
#define NPIX (NXD*NXD)     // 102400
#define P2B 4              // columns batched per pass-2 block

#define PADI(i) ((i) + ((i) >> 5))
#define NP 660             // PADI(639)=658 -> 660 floats per padded array

// Scratch (allocations are forbidden -> __device__ globals)
__device__ float2 d_grid[NFRAME*NCOIL*GD*GD];       // ~210 MB
__device__ float2 d_tmp1[NFRAME*NCOIL*GD*NXD];      // ~105 MB
__device__ float2 d_imcrop[NFRAME*NCOIL*NPIX];      // ~52 MB
__device__ float2 d_imt[NFRAME*NPIX];               // 8 x 320 x 320

// ---------------- radix-4 Stockham stage (sign +i), SoA padded shared ----------------
// Stage params: stride S, n = 640/S. 160 butterflies, one per thread lt in [0,160).
// read src[lt + j*160], write dst[4*S*p + q + j*S] * exp(+2pi i j p / n), p=lt/S, q=lt%S.
template<int S, int NN>
__device__ __forceinline__ void r4_stage(const float* __restrict__ sr, const float* __restrict__ si,
                                         float* __restrict__ dr, float* __restrict__ di, int lt)
{
    int q = lt % S, p = lt / S;
    float a0r = sr[PADI(lt)],       a0i = si[PADI(lt)];
    float a1r = sr[PADI(lt+160)],   a1i = si[PADI(lt+160)];
    float a2r = sr[PADI(lt+320)],   a2i = si[PADI(lt+320)];
    float a3r = sr[PADI(lt+480)],   a3i = si[PADI(lt+480)];

    float t0r=a0r+a2r, t0i=a0i+a2i;
    float t1r=a0r-a2r, t1i=a0i-a2i;
    float t2r=a1r+a3r, t2i=a1i+a3i;
    float t3r=a1r-a3r, t3i=a1i-a3i;

    float B0r=t0r+t2r, B0i=t0i+t2i;
    float B2r=t0r-t2r, B2i=t0i-t2i;
    float B1r=t1r-t3i, B1i=t1i+t3r;   // t1 + i*t3
    float B3r=t1r+t3i, B3i=t1i-t3r;   // t1 - i*t3

    float ang = (6.2831853071795864769f/(float)NN) * (float)p;
    float c1,s1,c2,s2,c3,s3;
    __sincosf(ang,        &s1,&c1);
    __sincosf(2.0f*ang,   &s2,&c2);
    __sincosf(3.0f*ang,   &s3,&c3);

    int w = 4*S*p + q;
    dr[PADI(w)]      = B0r;              di[PADI(w)]      = B0i;
    dr[PADI(w+S)]    = B1r*c1 - B1i*s1;  di[PADI(w+S)]    = B1r*s1 + B1i*c1;
    dr[PADI(w+2*S)]  = B2r*c2 - B2i*s2;  di[PADI(w+2*S)]  = B2r*s2 + B2i*c2;
    dr[PADI(w+3*S)]  = B3r*c3 - B3i*s3;  di[PADI(w+3*S)]  = B3r*s3 + B3i*c3;
}

// 640-pt inverse DFT (sign +, unnormalized). Input in (sr,si), OUTPUT in (dr,di).
// 160 threads per transform (lt in [0,160)). Stages: R5(s=1), R4(s=5), R4(s=20),
// R4(s=80), R2(s=320, twiddle-free). 5 stages -> result lands in (dr,di).
__device__ __forceinline__ void ifft640_soa(float* __restrict__ sr, float* __restrict__ si,
                                            float* __restrict__ dr, float* __restrict__ di, int lt)
{
    // ---- stage 1: radix-5, s=1, n=640 ----
    if (lt < 128) {
        int p = lt;
        float a0r = sr[PADI(p)],     a0i = si[PADI(p)];
        float a1r = sr[PADI(p+128)], a1i = si[PADI(p+128)];
        float a2r = sr[PADI(p+256)], a2i = si[PADI(p+256)];
        float a3r = sr[PADI(p+384)], a3i = si[PADI(p+384)];
        float a4r = sr[PADI(p+512)], a4i = si[PADI(p+512)];
        const float C1 =  0.3090169943749474241f;
        const float S1 =  0.9510565162951535721f;
        const float C2 = -0.8090169943749474241f;
        const float S2 =  0.5877852522924731292f;
        float t1r=a1r+a4r, t1i=a1i+a4i, t2r=a1r-a4r, t2i=a1i-a4i;
        float t3r=a2r+a3r, t3i=a2i+a3i, t4r=a2r-a3r, t4i=a2i-a3i;
        float b0r = a0r + t1r + t3r,  b0i = a0i + t1i + t3i;
        float m1r = a0r + C1*t1r + C2*t3r, m1i = a0i + C1*t1i + C2*t3i;
        float m2r = a0r + C2*t1r + C1*t3r, m2i = a0i + C2*t1i + C1*t3i;
        float n1r = S1*t2r + S2*t4r, n1i = S1*t2i + S2*t4i;
        float n2r = S2*t2r - S1*t4r, n2i = S2*t2i - S1*t4i;
        // sign +i: b_v = m +/- i*n
        float b1r = m1r - n1i, b1i = m1i + n1r;
        float b4r = m1r + n1i, b4i = m1i - n1r;
        float b2r = m2r - n2i, b2i = m2i + n2r;
        float b3r = m2r + n2i, b3i = m2i - n2r;
        float base = 6.2831853071795864769f * (float)p * (1.0f/640.0f);
        float s1w,c1w,s2w,c2w,s3w,c3w,s4w,c4w;
        __sincosf(base,      &s1w,&c1w);
        __sincosf(2.0f*base, &s2w,&c2w);
        __sincosf(3.0f*base, &s3w,&c3w);
        __sincosf(4.0f*base, &s4w,&c4w);
        dr[PADI(5*p)]   = b0r;                di[PADI(5*p)]   = b0i;
        dr[PADI(5*p+1)] = b1r*c1w - b1i*s1w;  di[PADI(5*p+1)] = b1r*s1w + b1i*c1w;
        dr[PADI(5*p+2)] = b2r*c2w - b2i*s2w;  di[PADI(5*p+2)] = b2r*s2w + b2i*c2w;
        dr[PADI(5*p+3)] = b3r*c3w - b3i*s3w;  di[PADI(5*p+3)] = b3r*s3w + b3i*c3w;
        dr[PADI(5*p+4)] = b4r*c4w - b4i*s4w;  di[PADI(5*p+4)] = b4r*s4w + b4i*c4w;
    }
    __syncthreads();

    r4_stage<5,128>(dr, di, sr, si, lt);   __syncthreads();
    r4_stage<20,32>(sr, si, dr, di, lt);   __syncthreads();
    r4_stage<80,8> (dr, di, sr, si, lt);   __syncthreads();

    // ---- stage 5: radix-2, s=320, twiddle-free ----
    #pragma unroll
    for (int k = 0; k < 2; k++) {
        int b = lt + k*160;
        float x0r = sr[PADI(b)],     x0i = si[PADI(b)];
        float x1r = sr[PADI(b+320)], x1i = si[PADI(b+320)];
        dr[PADI(b)]     = x0r + x1r;  di[PADI(b)]     = x0i + x1i;
        dr[PADI(b+320)] = x0r - x1r;  di[PADI(b+320)] = x0i - x1i;
    }
    __syncthreads();
}

// ---------------- kernels ----------------
__global__ void k_zero_grid()
{
    unsigned i = blockIdx.x * blockDim.x + threadIdx.x;
    const unsigned n = (unsigned)(NFRAME*NCOIL) * GD * GD / 2;   // float4 count
    if (i < n) reinterpret_cast<float4*>(d_grid)[i] = make_float4(0.f,0.f,0.f,0.f);
}

__device__ __forceinline__ void red_v2(float2* p, float re, float im)
{
    asm volatile("red.global.add.v2.f32 [%0], {%1, %2};" :: "l"(p), "f"(re), "f"(im) : "memory");
}

__global__ void k_scatter(const float* __restrict__ ksr, const float* __restrict__ ksi,
                          const float* __restrict__ traj, const float* __restrict__ dcf)
{
    int idx = blockIdx.x * blockDim.x + threadIdx.x;   // t*MS + m
    if (idx >= NFRAME * MS) return;
    int t = idx >> 16;
    int m = idx & (MS - 1);

    float u = (traj[m*2*NFRAME + 0*NFRAME + t] + 0.5f) * (float)GD;
    float v = (traj[m*2*NFRAME + 1*NFRAME + t] + 0.5f) * (float)GD;
    float w = dcf[m*NFRAME + t];

    float u0f = floorf(u), v0f = floorf(v);
    float du = u - u0f, dv = v - v0f;
    int i0 = (int)u0f; if (i0 >= GD) i0 -= GD;
    int j0 = (int)v0f; if (j0 >= GD) j0 -= GD;
    int i1 = i0 + 1; if (i1 >= GD) i1 -= GD;
    int j1 = j0 + 1; if (j1 >= GD) j1 -= GD;

    float w00 = (1.0f-du)*(1.0f-dv)*w;
    float w10 = du*(1.0f-dv)*w;
    float w01 = (1.0f-du)*dv*w;
    float w11 = du*dv*w;

    int o00 = i0*GD + j0, o10 = i1*GD + j0, o01 = i0*GD + j1, o11 = i1*GD + j1;

    #pragma unroll
    for (int c = 0; c < NCOIL; c++) {
        float kr = ksr[c*MS + m];
        float ki = ksi[c*MS + m];
        float2* g = d_grid + (size_t)(t*NCOIL + c) * GD * GD;
        red_v2(g + o00, kr*w00, ki*w00);
        red_v2(g + o10, kr*w10, ki*w10);
        red_v2(g + o01, kr*w01, ki*w01);
        red_v2(g + o11, kr*w11, ki*w11);
    }
}

// Pass 1: 2 rows per block (320 threads = 2 x 160). ifft along columns with
// input ifftshift, output fftshift + crop to 320 columns. Fully coalesced.
__global__ void k_fft_pass1()
{
    __shared__ float sR[2][NP], sI[2][NP], dR[2][NP], dI[2][NP];   // 21120 B
    int blk = blockIdx.x;
    int img = blk / (GD/2);
    int rp  = blk - img * (GD/2);
    int tid = threadIdx.x;
    int f   = tid / 160;          // which row of the pair
    int lt  = tid - f * 160;

    const float2* row = d_grid + ((size_t)img * GD + (2*rp + f)) * GD;
    #pragma unroll
    for (int k = 0; k < 4; k++) {
        int e = lt + k*160;
        int n = (e < NXD) ? (e + NXD) : (e - NXD);    // ifftshift
        float2 v = row[e];
        sR[f][PADI(n)] = v.x;  sI[f][PADI(n)] = v.y;
    }
    __syncthreads();

    ifft640_soa(sR[f], sI[f], dR[f], dI[f], lt);

    float2* orow = d_tmp1 + ((size_t)img * GD + (2*rp + f)) * NXD;
    #pragma unroll
    for (int k = 0; k < 2; k++) {
        int j = lt + k*160;
        int kk = (j < 160) ? (j + 480) : (j - 160);   // fftshift + crop
        orow[j] = make_float2(dR[f][PADI(kk)], dI[f][PADI(kk)]);
    }
}

// Pass 2: 4 columns per block, 2 FFTs concurrently x 2 iterations.
// Tile load/store coalesced (32B chunks). Crop + deapodize + 1/(G*G).
__global__ void k_fft_pass2()
{
    __shared__ float cR[P2B][NP], cI[P2B][NP];   // 21120 B
    __shared__ float pR[2][NP],  pI[2][NP];      // 10560 B
    int img = blockIdx.x / (NXD/P2B);
    int jb  = (blockIdx.x - img * (NXD/P2B)) * P2B;
    int tid = threadIdx.x;

    // Coalesced tile load with ifftshift folded into the shared row index.
    const float2* base = d_tmp1 + (size_t)img * GD * NXD + jb;
    #pragma unroll
    for (int it = 0; it < (GD*P2B)/NXD; it++) {
        int idx = it * NXD + tid;
        int r = idx >> 2;            // 0..639
        int c = idx & (P2B-1);       // 0..3
        int rr = (r < NXD) ? (r + NXD) : (r - NXD);
        float2 v = base[(size_t)r * NXD + c];
        cR[c][PADI(rr)] = v.x;  cI[c][PADI(rr)] = v.y;
    }
    __syncthreads();

    int f  = tid / 160;
    int lt = tid - f * 160;

    #pragma unroll 1
    for (int half = 0; half < 2; half++) {
        int c = half*2 + f;
        ifft640_soa(cR[c], cI[c], pR[f], pI[f], lt);

        // Write cropped+scaled result back into cR/cI[c] rows [0,320)
        int j = jb + c;
        float xj = (float)(j - 160) * (1.0f/640.0f);
        float dj;
        if (j == 160) { dj = 1.0f; } else { float px = 3.14159265358979324f * xj; float s = __sinf(px)/px; dj = s*s; }
        #pragma unroll
        for (int k = 0; k < 2; k++) {
            int i = lt + k*160;
            int kk = (i < 160) ? (i + 480) : (i - 160);
            float vr = pR[f][PADI(kk)], vi = pI[f][PADI(kk)];
            float xi = (float)(i - 160) * (1.0f/640.0f);
            float di2;
            if (i == 160) { di2 = 1.0f; } else { float px = 3.14159265358979324f * xi; float s = __sinf(px)/px; di2 = s*s; }
            float scale = 1.0f / (409600.0f * di2 * dj);
            cR[c][PADI(i)] = vr * scale;
            cI[c][PADI(i)] = vi * scale;
        }
        __syncthreads();   // ping buffers reused next iteration
    }

    // Coalesced tile store.
    float2* obase = d_imcrop + (size_t)img * NPIX + jb;
    #pragma unroll
    for (int it = 0; it < (NXD*P2B)/NXD; it++) {
        int idx = it * NXD + tid;
        int i = idx >> 2;
        int c = idx & (P2B-1);
        obase[(size_t)i * NXD + c] = make_float2(cR[c][PADI(i)], cI[c][PADI(i)]);
    }
}

// Coil combine: imt[t][pix] = sum_c conj(csm[c]) * im[t][c]
__global__ void k_combine(const float* __restrict__ csr, const float* __restrict__ csi)
{
    int idx = blockIdx.x * blockDim.x + threadIdx.x;   // t*NPIX + pix
    if (idx >= NFRAME * NPIX) return;
    int t = idx / NPIX;
    int pix = idx - t * NPIX;
    float re = 0.f, im = 0.f;
    #pragma unroll
    for (int c = 0; c < NCOIL; c++) {
        float2 v = d_imcrop[(size_t)(t*NCOIL + c) * NPIX + pix];
        float cr = csr[c*NPIX + pix];
        float ci = csi[c*NPIX + pix];
        re += cr*v.x + ci*v.y;
        im += cr*v.y - ci*v.x;
    }
    d_imt[idx] = make_float2(re, im);
}

// Motion warp each frame and sum over frames.
__global__ void k_warp_sum(const float* __restrict__ motions, float* __restrict__ out)
{
    int idx = blockIdx.x * blockDim.x + threadIdx.x;   // x*NXD + y
    if (idx >= NPIX) return;
    int x = idx / NXD;
    int y = idx - x * NXD;

    float accr = 0.f, acci = 0.f;
    #pragma unroll
    for (int t = 0; t < NFRAME; t++) {
        float fx = (float)x + motions[(idx*2 + 0)*NFRAME + t];
        float fy = (float)y + motions[(idx*2 + 1)*NFRAME + t];
        fx = fminf(fmaxf(fx, 0.0f), (float)(NXD-1));
        fy = fminf(fmaxf(fy, 0.0f), (float)(NXD-1));
        int x0 = (int)floorf(fx);
        int y0 = (int)floorf(fy);
        int x1 = min(x0 + 1, NXD-1);
        int y1 = min(y0 + 1, NXD-1);
        float dx = fx - (float)x0;
        float dy = fy - (float)y0;
        const float2* im = d_imt + (size_t)t * NPIX;
        float2 v00 = im[x0*NXD + y0];
        float2 v10 = im[x1*NXD + y0];
        float2 v01 = im[x0*NXD + y1];
        float2 v11 = im[x1*NXD + y1];
        float w00 = (1.f-dx)*(1.f-dy), w10 = dx*(1.f-dy), w01 = (1.f-dx)*dy, w11 = dx*dy;
        accr += w00*v00.x + w10*v10.x + w01*v01.x + w11*v11.x;
        acci += w00*v00.y + w10*v10.y + w01*v01.y + w11*v11.y;
    }
    out[idx*2 + 0] = accr;
    out[idx*2 + 1] = acci;
}

// ---------------- launch ----------------
extern "C" void kernel_launch(void* const* d_in, const int* in_sizes, int n_in,
                              void* d_out, int out_size)
{
    const float* ksr     = (const float*)d_in[0];
    const float* ksi     = (const float*)d_in[1];
    const float* traj    = (const float*)d_in[2];
    const float* csr     = (const float*)d_in[3];
    const float* csi     = (const float*)d_in[4];
    const float* dcf     = (const float*)d_in[5];
    const float* motions = (const float*)d_in[6];
    float* out = (float*)d_out;

    const int nzero = NFRAME*NCOIL*GD*GD/2;                 // float4 elements
    k_zero_grid<<<(nzero + 255)/256, 256>>>();
    k_scatter<<<(NFRAME*MS + 255)/256, 256>>>(ksr, ksi, traj, dcf);
    k_fft_pass1<<<NFRAME*NCOIL*(GD/2), NXD>>>();
    k_fft_pass2<<<NFRAME*NCOIL*(NXD/P2B), NXD>>>();
    k_combine<<<(NFRAME*NPIX + 255)/256, 256>>>(csr, csi);
    k_warp_sum<<<(NPIX + 255)/256, 256>>>(motions, out);
}

// round 4
// speedup vs baseline: 1.6137x; 1.0508x over previous
#include <cuda_runtime.h>
#include <cuda_bf16.h>
#include <math.h>

// Problem constants
#define NXD 320
#define GD  640            // OS*NX
#define NCOIL 8
#define NFRAME 8
#define MS 65536
#define NPIX (NXD*NXD)     // 102400
#define P2B 4              // columns batched per pass-2 block

#define PADI(i) ((i) + ((i) >> 5))
#define NP 660             // PADI(639)=658 -> 660 floats per padded array

// Scratch (allocations are forbidden -> __device__ globals)
// d_grid layout: [t][i][j][coil] as float2, declared float4 for 16B alignment.
__device__ float4 d_grid4[(size_t)NFRAME*GD*GD*NCOIL/2];   // ~210 MB
__device__ float2 d_tmp1[(size_t)NFRAME*NCOIL*GD*NXD];     // ~105 MB  [img][r][j]
__device__ float2 d_imcrop[(size_t)NFRAME*NCOIL*NPIX];     // ~52 MB
__device__ float2 d_imt[NFRAME*NPIX];                      // 8 x 320 x 320

// ---------------- radix-4 Stockham stage (sign +i), SoA padded shared ----------------
template<int S, int NN>
__device__ __forceinline__ void r4_stage(const float* __restrict__ sr, const float* __restrict__ si,
                                         float* __restrict__ dr, float* __restrict__ di, int lt)
{
    int q = lt % S, p = lt / S;
    float a0r = sr[PADI(lt)],       a0i = si[PADI(lt)];
    float a1r = sr[PADI(lt+160)],   a1i = si[PADI(lt+160)];
    float a2r = sr[PADI(lt+320)],   a2i = si[PADI(lt+320)];
    float a3r = sr[PADI(lt+480)],   a3i = si[PADI(lt+480)];

    float t0r=a0r+a2r, t0i=a0i+a2i;
    float t1r=a0r-a2r, t1i=a0i-a2i;
    float t2r=a1r+a3r, t2i=a1i+a3i;
    float t3r=a1r-a3r, t3i=a1i-a3i;

    float B0r=t0r+t2r, B0i=t0i+t2i;
    float B2r=t0r-t2r, B2i=t0i-t2i;
    float B1r=t1r-t3i, B1i=t1i+t3r;   // t1 + i*t3
    float B3r=t1r+t3i, B3i=t1i-t3r;   // t1 - i*t3

    float ang = (6.2831853071795864769f/(float)NN) * (float)p;
    float c1,s1;
    __sincosf(ang, &s1, &c1);
    float c2 = c1*c1 - s1*s1, s2 = 2.0f*c1*s1;          // w^2
    float c3 = c2*c1 - s2*s1, s3 = c2*s1 + s2*c1;       // w^3

    int w = 4*S*p + q;
    dr[PADI(w)]      = B0r;              di[PADI(w)]      = B0i;
    dr[PADI(w+S)]    = B1r*c1 - B1i*s1;  di[PADI(w+S)]    = B1r*s1 + B1i*c1;
    dr[PADI(w+2*S)]  = B2r*c2 - B2i*s2;  di[PADI(w+2*S)]  = B2r*s2 + B2i*c2;
    dr[PADI(w+3*S)]  = B3r*c3 - B3i*s3;  di[PADI(w+3*S)]  = B3r*s3 + B3i*c3;
}

// 640-pt inverse DFT (sign +, unnormalized). Input in (sr,si) [clobbered],
// OUTPUT in (dr,di). 160 threads per transform, lt in [0,160).
__device__ __forceinline__ void ifft640_soa(float* __restrict__ sr, float* __restrict__ si,
                                            float* __restrict__ dr, float* __restrict__ di, int lt)
{
    // ---- stage 1: radix-5, s=1, n=640 ----
    if (lt < 128) {
        int p = lt;
        float a0r = sr[PADI(p)],     a0i = si[PADI(p)];
        float a1r = sr[PADI(p+128)], a1i = si[PADI(p+128)];
        float a2r = sr[PADI(p+256)], a2i = si[PADI(p+256)];
        float a3r = sr[PADI(p+384)], a3i = si[PADI(p+384)];
        float a4r = sr[PADI(p+512)], a4i = si[PADI(p+512)];
        const float C1 =  0.3090169943749474241f;
        const float S1 =  0.9510565162951535721f;
        const float C2 = -0.8090169943749474241f;
        const float S2 =  0.5877852522924731292f;
        float t1r=a1r+a4r, t1i=a1i+a4i, t2r=a1r-a4r, t2i=a1i-a4i;
        float t3r=a2r+a3r, t3i=a2i+a3i, t4r=a2r-a3r, t4i=a2i-a3i;
        float b0r = a0r + t1r + t3r,  b0i = a0i + t1i + t3i;
        float m1r = a0r + C1*t1r + C2*t3r, m1i = a0i + C1*t1i + C2*t3i;
        float m2r = a0r + C2*t1r + C1*t3r, m2i = a0i + C2*t1i + C1*t3i;
        float n1r = S1*t2r + S2*t4r, n1i = S1*t2i + S2*t4i;
        float n2r = S2*t2r - S1*t4r, n2i = S2*t2i - S1*t4i;
        float b1r = m1r - n1i, b1i = m1i + n1r;
        float b4r = m1r + n1i, b4i = m1i - n1r;
        float b2r = m2r - n2i, b2i = m2i + n2r;
        float b3r = m2r + n2i, b3i = m2i - n2r;
        float base = 6.2831853071795864769f * (float)p * (1.0f/640.0f);
        float c1w,s1w;
        __sincosf(base, &s1w, &c1w);
        float c2w = c1w*c1w - s1w*s1w, s2w = 2.0f*c1w*s1w;
        float c3w = c2w*c1w - s2w*s1w, s3w = c2w*s1w + s2w*c1w;
        float c4w = c2w*c2w - s2w*s2w, s4w = 2.0f*c2w*s2w;
        dr[PADI(5*p)]   = b0r;                di[PADI(5*p)]   = b0i;
        dr[PADI(5*p+1)] = b1r*c1w - b1i*s1w;  di[PADI(5*p+1)] = b1r*s1w + b1i*c1w;
        dr[PADI(5*p+2)] = b2r*c2w - b2i*s2w;  di[PADI(5*p+2)] = b2r*s2w + b2i*c2w;
        dr[PADI(5*p+3)] = b3r*c3w - b3i*s3w;  di[PADI(5*p+3)] = b3r*s3w + b3i*c3w;
        dr[PADI(5*p+4)] = b4r*c4w - b4i*s4w;  di[PADI(5*p+4)] = b4r*s4w + b4i*c4w;
    }
    __syncthreads();

    r4_stage<5,128>(dr, di, sr, si, lt);   __syncthreads();
    r4_stage<20,32>(sr, si, dr, di, lt);   __syncthreads();
    r4_stage<80,8> (dr, di, sr, si, lt);   __syncthreads();

    // ---- stage 5: radix-2, s=320, twiddle-free ----
    #pragma unroll
    for (int k = 0; k < 2; k++) {
        int b = lt + k*160;
        float x0r = sr[PADI(b)],     x0i = si[PADI(b)];
        float x1r = sr[PADI(b+320)], x1i = si[PADI(b+320)];
        dr[PADI(b)]     = x0r + x1r;  di[PADI(b)]     = x0i + x1i;
        dr[PADI(b+320)] = x0r - x1r;  di[PADI(b+320)] = x0i - x1i;
    }
    __syncthreads();
}

// ---------------- kernels ----------------
__global__ void k_zero_grid()
{
    unsigned i = blockIdx.x * blockDim.x + threadIdx.x;
    const unsigned n = (unsigned)(NFRAME*NCOIL) * GD * GD / 2;   // float4 count
    if (i < n) d_grid4[i] = make_float4(0.f,0.f,0.f,0.f);
}

__device__ __forceinline__ void red_v4(float* p, float a, float b, float c, float d)
{
    asm volatile("red.global.add.v4.f32 [%0], {%1, %2, %3, %4};"
                 :: "l"(p), "f"(a), "f"(b), "f"(c), "f"(d) : "memory");
}

__global__ void k_scatter(const float* __restrict__ ksr, const float* __restrict__ ksi,
                          const float* __restrict__ traj, const float* __restrict__ dcf)
{
    int idx = blockIdx.x * blockDim.x + threadIdx.x;   // t*MS + m
    if (idx >= NFRAME * MS) return;
    int t = idx >> 16;
    int m = idx & (MS - 1);

    float u = (traj[m*2*NFRAME + 0*NFRAME + t] + 0.5f) * (float)GD;
    float v = (traj[m*2*NFRAME + 1*NFRAME + t] + 0.5f) * (float)GD;
    float w = dcf[m*NFRAME + t];

    float u0f = floorf(u), v0f = floorf(v);
    float du = u - u0f, dv = v - v0f;
    int i0 = (int)u0f; if (i0 >= GD) i0 -= GD;
    int j0 = (int)v0f; if (j0 >= GD) j0 -= GD;
    int i1 = i0 + 1; if (i1 >= GD) i1 -= GD;
    int j1 = j0 + 1; if (j1 >= GD) j1 -= GD;

    float wc[4];
    wc[0] = (1.0f-du)*(1.0f-dv)*w;   // (i0,j0)
    wc[1] = du*(1.0f-dv)*w;          // (i1,j0)
    wc[2] = (1.0f-du)*dv*w;          // (i0,j1)
    wc[3] = du*dv*w;                 // (i1,j1)
    size_t oc[4];
    oc[0] = ((size_t)i0*GD + j0) * NCOIL;
    oc[1] = ((size_t)i1*GD + j0) * NCOIL;
    oc[2] = ((size_t)i0*GD + j1) * NCOIL;
    oc[3] = ((size_t)i1*GD + j1) * NCOIL;

    float kr[NCOIL], ki[NCOIL];
    #pragma unroll
    for (int c = 0; c < NCOIL; c++) { kr[c] = ksr[c*MS + m]; ki[c] = ksi[c*MS + m]; }

    float* gbase = (float*)(d_grid4) + (size_t)t * GD * GD * NCOIL * 2;
    #pragma unroll
    for (int k = 0; k < 4; k++) {
        float* p = gbase + oc[k]*2;
        float ww = wc[k];
        #pragma unroll
        for (int h = 0; h < 4; h++) {
            red_v4(p + 4*h, kr[2*h]*ww, ki[2*h]*ww, kr[2*h+1]*ww, ki[2*h+1]*ww);
        }
    }
}

// Pass 1: one block per (t, row r), all 8 coils. Loads the 8-coil row (40KB
// contiguous), runs 8 column-FFTs (2 concurrently x 4), writes cropped rows.
__global__ void __launch_bounds__(NXD, 4) k_fft_pass1()
{
    __shared__ float cR[NCOIL][NP], cI[NCOIL][NP];   // 42240 B
    __shared__ float pR[2][NP],  pI[2][NP];          // 10560 B
    int t = blockIdx.x / GD;
    int r = blockIdx.x - t * GD;
    int tid = threadIdx.x;

    const float2* row = (const float2*)d_grid4 + ((size_t)t*GD + r) * GD * NCOIL;
    #pragma unroll
    for (int it = 0; it < (GD*NCOIL)/NXD; it++) {
        int idx = it * NXD + tid;
        int j = idx >> 3;          // 0..639
        int c = idx & 7;           // coil
        int jsh = (j < NXD) ? (j + NXD) : (j - NXD);    // ifftshift
        float2 v = row[idx];
        cR[c][PADI(jsh)] = v.x;  cI[c][PADI(jsh)] = v.y;
    }
    __syncthreads();

    int f  = tid / 160;
    int lt = tid - f * 160;

    #pragma unroll 1
    for (int it = 0; it < 4; it++) {
        int c = it*2 + f;
        ifft640_soa(cR[c], cI[c], pR[f], pI[f], lt);

        float2* orow = d_tmp1 + ((size_t)(t*NCOIL + c) * GD + r) * NXD;
        #pragma unroll
        for (int k = 0; k < 2; k++) {
            int j = lt + k*160;
            int kk = (j < 160) ? (j + 480) : (j - 160);   // fftshift + crop
            orow[j] = make_float2(pR[f][PADI(kk)], pI[f][PADI(kk)]);
        }
        __syncthreads();   // ping buffers reused next iteration
    }
}

// Pass 2: 4 columns per block, 2 FFTs concurrently x 2 iterations.
__global__ void __launch_bounds__(NXD, 4) k_fft_pass2()
{
    __shared__ float cR[P2B][NP], cI[P2B][NP];   // 21120 B
    __shared__ float pR[2][NP],  pI[2][NP];      // 10560 B
    int img = blockIdx.x / (NXD/P2B);
    int jb  = (blockIdx.x - img * (NXD/P2B)) * P2B;
    int tid = threadIdx.x;

    const float2* base = d_tmp1 + (size_t)img * GD * NXD + jb;
    #pragma unroll
    for (int it = 0; it < (GD*P2B)/NXD; it++) {
        int idx = it * NXD + tid;
        int r = idx >> 2;            // 0..639
        int c = idx & (P2B-1);       // 0..3
        int rr = (r < NXD) ? (r + NXD) : (r - NXD);
        float2 v = base[(size_t)r * NXD + c];
        cR[c][PADI(rr)] = v.x;  cI[c][PADI(rr)] = v.y;
    }
    __syncthreads();

    int f  = tid / 160;
    int lt = tid - f * 160;

    #pragma unroll 1
    for (int half = 0; half < 2; half++) {
        int c = half*2 + f;
        ifft640_soa(cR[c], cI[c], pR[f], pI[f], lt);

        int j = jb + c;
        float xj = (float)(j - 160) * (1.0f/640.0f);
        float dj;
        if (j == 160) { dj = 1.0f; } else { float px = 3.14159265358979324f * xj; float s = __sinf(px)/px; dj = s*s; }
        #pragma unroll
        for (int k = 0; k < 2; k++) {
            int i = lt + k*160;
            int kk = (i < 160) ? (i + 480) : (i - 160);
            float vr = pR[f][PADI(kk)], vi = pI[f][PADI(kk)];
            float xi = (float)(i - 160) * (1.0f/640.0f);
            float di2;
            if (i == 160) { di2 = 1.0f; } else { float px = 3.14159265358979324f * xi; float s = __sinf(px)/px; di2 = s*s; }
            float scale = 1.0f / (409600.0f * di2 * dj);
            cR[c][PADI(i)] = vr * scale;
            cI[c][PADI(i)] = vi * scale;
        }
        __syncthreads();
    }

    float2* obase = d_imcrop + (size_t)img * NPIX + jb;
    #pragma unroll
    for (int it = 0; it < (NXD*P2B)/NXD; it++) {
        int idx = it * NXD + tid;
        int i = idx >> 2;
        int c = idx & (P2B-1);
        obase[(size_t)i * NXD + c] = make_float2(cR[c][PADI(i)], cI[c][PADI(i)]);
    }
}

// Coil combine: imt[t][pix] = sum_c conj(csm[c]) * im[t][c]
__global__ void k_combine(const float* __restrict__ csr, const float* __restrict__ csi)
{
    int idx = blockIdx.x * blockDim.x + threadIdx.x;   // t*NPIX + pix
    if (idx >= NFRAME * NPIX) return;
    int t = idx / NPIX;
    int pix = idx - t * NPIX;
    float re = 0.f, im = 0.f;
    #pragma unroll
    for (int c = 0; c < NCOIL; c++) {
        float2 v = d_imcrop[(size_t)(t*NCOIL + c) * NPIX + pix];
        float cr = csr[c*NPIX + pix];
        float ci = csi[c*NPIX + pix];
        re += cr*v.x + ci*v.y;
        im += cr*v.y - ci*v.x;
    }
    d_imt[idx] = make_float2(re, im);
}

// Motion warp each frame and sum over frames.
__global__ void k_warp_sum(const float* __restrict__ motions, float* __restrict__ out)
{
    int idx = blockIdx.x * blockDim.x + threadIdx.x;   // x*NXD + y
    if (idx >= NPIX) return;
    int x = idx / NXD;
    int y = idx - x * NXD;

    float accr = 0.f, acci = 0.f;
    #pragma unroll
    for (int t = 0; t < NFRAME; t++) {
        float fx = (float)x + motions[(idx*2 + 0)*NFRAME + t];
        float fy = (float)y + motions[(idx*2 + 1)*NFRAME + t];
        fx = fminf(fmaxf(fx, 0.0f), (float)(NXD-1));
        fy = fminf(fmaxf(fy, 0.0f), (float)(NXD-1));
        int x0 = (int)floorf(fx);
        int y0 = (int)floorf(fy);
        int x1 = min(x0 + 1, NXD-1);
        int y1 = min(y0 + 1, NXD-1);
        float dx = fx - (float)x0;
        float dy = fy - (float)y0;
        const float2* im = d_imt + (size_t)t * NPIX;
        float2 v00 = im[x0*NXD + y0];
        float2 v10 = im[x1*NXD + y0];
        float2 v01 = im[x0*NXD + y1];
        float2 v11 = im[x1*NXD + y1];
        float w00 = (1.f-dx)*(1.f-dy), w10 = dx*(1.f-dy), w01 = (1.f-dx)*dy, w11 = dx*dy;
        accr += w00*v00.x + w10*v10.x + w01*v01.x + w11*v11.x;
        acci += w00*v00.y + w10*v10.y + w01*v01.y + w11*v11.y;
    }
    out[idx*2 + 0] = accr;
    out[idx*2 + 1] = acci;
}

// ---------------- launch ----------------
extern "C" void kernel_launch(void* const* d_in, const int* in_sizes, int n_in,
                              void* d_out, int out_size)
{
    const float* ksr     = (const float*)d_in[0];
    const float* ksi     = (const float*)d_in[1];
    const float* traj    = (const float*)d_in[2];
    const float* csr     = (const float*)d_in[3];
    const float* csi     = (const float*)d_in[4];
    const float* dcf     = (const float*)d_in[5];
    const float* motions = (const float*)d_in[6];
    float* out = (float*)d_out;

    const int nzero = NFRAME*NCOIL*GD*GD/2;                 // float4 elements
    k_zero_grid<<<(nzero + 255)/256, 256>>>();
    k_scatter<<<(NFRAME*MS + 255)/256, 256>>>(ksr, ksi, traj, dcf);
    k_fft_pass1<<<NFRAME*GD, NXD>>>();
    k_fft_pass2<<<NFRAME*NCOIL*(NXD/P2B), NXD>>>();
    k_combine<<<(NFRAME*NPIX + 255)/256, 256>>>(csr, csi);
    k_warp_sum<<<(NPIX + 255)/256, 256>>>(motions, out);
}

// round 9
// speedup vs baseline: 2.2385x; 1.3872x over previous
#include <cuda_runtime.h>
#include <cuda_bf16.h>
#include <math.h>

// Problem constants
#define NXD 320
#define GD  640            // OS*NX
#define NCOIL 8
#define NFRAME 8
#define MS 65536
#define NPIX (NXD*NXD)     // 102400

#define PADI8(i) ((i) + ((i) >> 3))
#define NP8 728            // PADI8(639)=718, padded to 728 (mod 32 == 24)

// Scratch (allocations are forbidden -> __device__ globals)
// d_grid layout: [t][i][j][coil] as float2, declared float4 for 16B alignment.
__device__ float4 d_grid4[(size_t)NFRAME*GD*GD*NCOIL/2];   // ~210 MB
__device__ float2 d_tmp1[(size_t)NFRAME*NCOIL*GD*NXD];     // ~105 MB  [img][r][j]
__device__ float2 d_imcrop[(size_t)NFRAME*NCOIL*NPIX];     // ~52 MB
__device__ float2 d_imt[NFRAME*NPIX];                      // 8 x 320 x 320

// ---------------- radix-8 butterfly (sign +i) ----------------
// b_k = sum_j a_j e^{+2pi i jk/8}. DIT 2x4.
#define RADIX8_BODY() \
    float t0r=a0r+a4r, t0i=a0i+a4i; \
    float t1r=a0r-a4r, t1i=a0i-a4i; \
    float t2r=a2r+a6r, t2i=a2i+a6i; \
    float t3r=a2r-a6r, t3i=a2i-a6i; \
    float E0r=t0r+t2r, E0i=t0i+t2i; \
    float E2r=t0r-t2r, E2i=t0i-t2i; \
    float E1r=t1r-t3i, E1i=t1i+t3r; \
    float E3r=t1r+t3i, E3i=t1i-t3r; \
    float u0r=a1r+a5r, u0i=a1i+a5i; \
    float u1r=a1r-a5r, u1i=a1i-a5i; \
    float u2r=a3r+a7r, u2i=a3i+a7i; \
    float u3r=a3r-a7r, u3i=a3i-a7i; \
    float O0r=u0r+u2r, O0i=u0i+u2i; \
    float O2r=u0r-u2r, O2i=u0i-u2i; \
    float O1r=u1r-u3i, O1i=u1i+u3r; \
    float O3r=u1r+u3i, O3i=u1i-u3r; \
    const float RS2 = 0.70710678118654752440f; \
    float W1r = RS2*(O1r - O1i), W1i = RS2*(O1r + O1i); \
    float W2r = -O2i,            W2i = O2r; \
    float W3r = -RS2*(O3r + O3i), W3i = RS2*(O3r - O3i); \
    float b0r=E0r+O0r, b0i=E0i+O0i, b4r=E0r-O0r, b4i=E0i-O0i; \
    float b1r=E1r+W1r, b1i=E1i+W1i, b5r=E1r-W1r, b5i=E1i-W1i; \
    float b2r=E2r+W2r, b2i=E2i+W2i, b6r=E2r-W2r, b6i=E2i-W2i; \
    float b3r=E3r+W3r, b3i=E3i+W3i, b7r=E3r-W3r, b7i=E3i-W3i;

// complex multiply helper for twiddle application (b * w)
#define CMULW(br,bi,cr,ci, outr,outi) { outr = br*cr - bi*ci; outi = br*ci + bi*cr; }

// ---------------- stage 1: radix-8, S=1, n=640 ----------------
// read src[lt + 80j]; write dst[8*lt + k] * e^{+2pi i k lt/640}
__device__ __forceinline__ void s1_r8(const float* __restrict__ sr, const float* __restrict__ si,
                                      float* __restrict__ dr, float* __restrict__ di, int lt)
{
    float a0r=sr[PADI8(lt)],     a0i=si[PADI8(lt)];
    float a1r=sr[PADI8(lt+80)],  a1i=si[PADI8(lt+80)];
    float a2r=sr[PADI8(lt+160)], a2i=si[PADI8(lt+160)];
    float a3r=sr[PADI8(lt+240)], a3i=si[PADI8(lt+240)];
    float a4r=sr[PADI8(lt+320)], a4i=si[PADI8(lt+320)];
    float a5r=sr[PADI8(lt+400)], a5i=si[PADI8(lt+400)];
    float a6r=sr[PADI8(lt+480)], a6i=si[PADI8(lt+480)];
    float a7r=sr[PADI8(lt+560)], a7i=si[PADI8(lt+560)];
    RADIX8_BODY();

    float base = 6.2831853071795864769f * (1.0f/640.0f) * (float)lt;
    float c1,s1;  __sincosf(base, &s1, &c1);
    float c2=c1*c1-s1*s1, s2=2.0f*c1*s1;
    float c3=c1*c2-s1*s2, s3=c1*s2+s1*c2;
    float c4=c2*c2-s2*s2, s4=2.0f*c2*s2;
    float c5=c2*c3-s2*s3, s5=c2*s3+s2*c3;
    float c6=c3*c3-s3*s3, s6=2.0f*c3*s3;
    float c7=c3*c4-s3*s4, s7=c3*s4+s3*c4;

    int w = 8*lt;
    float xr, xi;
    dr[PADI8(w)]   = b0r;  di[PADI8(w)]   = b0i;
    CMULW(b1r,b1i,c1,s1,xr,xi); dr[PADI8(w+1)] = xr; di[PADI8(w+1)] = xi;
    CMULW(b2r,b2i,c2,s2,xr,xi); dr[PADI8(w+2)] = xr; di[PADI8(w+2)] = xi;
    CMULW(b3r,b3i,c3,s3,xr,xi); dr[PADI8(w+3)] = xr; di[PADI8(w+3)] = xi;
    CMULW(b4r,b4i,c4,s4,xr,xi); dr[PADI8(w+4)] = xr; di[PADI8(w+4)] = xi;
    CMULW(b5r,b5i,c5,s5,xr,xi); dr[PADI8(w+5)] = xr; di[PADI8(w+5)] = xi;
    CMULW(b6r,b6i,c6,s6,xr,xi); dr[PADI8(w+6)] = xr; di[PADI8(w+6)] = xi;
    CMULW(b7r,b7i,c7,s7,xr,xi); dr[PADI8(w+7)] = xr; di[PADI8(w+7)] = xi;
}

// ---------------- stage 2: radix-8, S=8, n=80 ----------------
// q=lt%8, p=lt/8. read src[lt + 80j]; write dst[64p + q + 8k] * e^{+2pi i k p/80}
__device__ __forceinline__ void s2_r8(const float* __restrict__ sr, const float* __restrict__ si,
                                      float* __restrict__ dr, float* __restrict__ di, int lt)
{
    int q = lt & 7, p = lt >> 3;
    float a0r=sr[PADI8(lt)],     a0i=si[PADI8(lt)];
    float a1r=sr[PADI8(lt+80)],  a1i=si[PADI8(lt+80)];
    float a2r=sr[PADI8(lt+160)], a2i=si[PADI8(lt+160)];
    float a3r=sr[PADI8(lt+240)], a3i=si[PADI8(lt+240)];
    float a4r=sr[PADI8(lt+320)], a4i=si[PADI8(lt+320)];
    float a5r=sr[PADI8(lt+400)], a5i=si[PADI8(lt+400)];
    float a6r=sr[PADI8(lt+480)], a6i=si[PADI8(lt+480)];
    float a7r=sr[PADI8(lt+560)], a7i=si[PADI8(lt+560)];
    RADIX8_BODY();

    float base = 6.2831853071795864769f * (1.0f/80.0f) * (float)p;
    float c1,s1;  __sincosf(base, &s1, &c1);
    float c2=c1*c1-s1*s1, s2=2.0f*c1*s1;
    float c3=c1*c2-s1*s2, s3=c1*s2+s1*c2;
    float c4=c2*c2-s2*s2, s4=2.0f*c2*s2;
    float c5=c2*c3-s2*s3, s5=c2*s3+s2*c3;
    float c6=c3*c3-s3*s3, s6=2.0f*c3*s3;
    float c7=c3*c4-s3*s4, s7=c3*s4+s3*c4;

    int w = 64*p + q;
    float xr, xi;
    dr[PADI8(w)]    = b0r;  di[PADI8(w)]    = b0i;
    CMULW(b1r,b1i,c1,s1,xr,xi); dr[PADI8(w+8)]  = xr; di[PADI8(w+8)]  = xi;
    CMULW(b2r,b2i,c2,s2,xr,xi); dr[PADI8(w+16)] = xr; di[PADI8(w+16)] = xi;
    CMULW(b3r,b3i,c3,s3,xr,xi); dr[PADI8(w+24)] = xr; di[PADI8(w+24)] = xi;
    CMULW(b4r,b4i,c4,s4,xr,xi); dr[PADI8(w+32)] = xr; di[PADI8(w+32)] = xi;
    CMULW(b5r,b5i,c5,s5,xr,xi); dr[PADI8(w+40)] = xr; di[PADI8(w+40)] = xi;
    CMULW(b6r,b6i,c6,s6,xr,xi); dr[PADI8(w+48)] = xr; di[PADI8(w+48)] = xi;
    CMULW(b7r,b7i,c7,s7,xr,xi); dr[PADI8(w+56)] = xr; di[PADI8(w+56)] = xi;
}

// ---------------- stage 3: radix-10, S=64, twiddle-free ----------------
// lt in [0,64). reads src[lt + 64j], j=0..9. Outputs X[lt + 64k].
// DFT5 (sign +i)
#define DFT5M(x0r,x0i,x1r,x1i,x2r,x2i,x3r,x3i,x4r,x4i, X0r,X0i,X1r,X1i,X2r,X2i,X3r,X3i,X4r,X4i) { \
    const float C1 =  0.3090169943749474241f; \
    const float S1 =  0.9510565162951535721f; \
    const float C2 = -0.8090169943749474241f; \
    const float S2 =  0.5877852522924731292f; \
    float t1r=x1r+x4r, t1i=x1i+x4i, t2r=x1r-x4r, t2i=x1i-x4i; \
    float t3r=x2r+x3r, t3i=x2i+x3i, t4r=x2r-x3r, t4i=x2i-x3i; \
    X0r = x0r + t1r + t3r;  X0i = x0i + t1i + t3i; \
    float m1r = x0r + C1*t1r + C2*t3r, m1i = x0i + C1*t1i + C2*t3i; \
    float m2r = x0r + C2*t1r + C1*t3r, m2i = x0i + C2*t1i + C1*t3i; \
    float n1r = S1*t2r + S2*t4r, n1i = S1*t2i + S2*t4i; \
    float n2r = S2*t2r - S1*t4r, n2i = S2*t2i - S1*t4i; \
    X1r = m1r - n1i;  X1i = m1i + n1r; \
    X4r = m1r + n1i;  X4i = m1i - n1r; \
    X2r = m2r - n2i;  X2i = m2i + n2r; \
    X3r = m2r + n2i;  X3i = m2i - n2r; \
}

// computes b0..b9 from src; leaves them in provided float refs
#define STAGE3_LOAD_AND_BFLY() \
    float a0r=sr[PADI8(lt)],     a0i=si[PADI8(lt)]; \
    float a1r=sr[PADI8(lt+64)],  a1i=si[PADI8(lt+64)]; \
    float a2r=sr[PADI8(lt+128)], a2i=si[PADI8(lt+128)]; \
    float a3r=sr[PADI8(lt+192)], a3i=si[PADI8(lt+192)]; \
    float a4r=sr[PADI8(lt+256)], a4i=si[PADI8(lt+256)]; \
    float a5r=sr[PADI8(lt+320)], a5i=si[PADI8(lt+320)]; \
    float a6r=sr[PADI8(lt+384)], a6i=si[PADI8(lt+384)]; \
    float a7r=sr[PADI8(lt+448)], a7i=si[PADI8(lt+448)]; \
    float a8r=sr[PADI8(lt+512)], a8i=si[PADI8(lt+512)]; \
    float a9r=sr[PADI8(lt+576)], a9i=si[PADI8(lt+576)]; \
    float E0r,E0i,E1r,E1i,E2r,E2i,E3r,E3i,E4r,E4i; \
    float O0r,O0i,O1r,O1i,O2r,O2i,O3r,O3i,O4r,O4i; \
    DFT5M(a0r,a0i,a2r,a2i,a4r,a4i,a6r,a6i,a8r,a8i, E0r,E0i,E1r,E1i,E2r,E2i,E3r,E3i,E4r,E4i); \
    DFT5M(a1r,a1i,a3r,a3i,a5r,a5i,a7r,a7i,a9r,a9i, O0r,O0i,O1r,O1i,O2r,O2i,O3r,O3i,O4r,O4i); \
    const float W1R=0.8090169943749474241f,  W1I=0.5877852522924731292f; \
    const float W2R=0.3090169943749474241f,  W2I=0.9510565162951535721f; \
    const float W3R=-0.3090169943749474241f, W3I=0.9510565162951535721f; \
    const float W4R=-0.8090169943749474241f, W4I=0.5877852522924731292f; \
    float P1r,P1i,P2r,P2i,P3r,P3i,P4r,P4i; \
    CMULW(O1r,O1i,W1R,W1I,P1r,P1i); \
    CMULW(O2r,O2i,W2R,W2I,P2r,P2i); \
    CMULW(O3r,O3i,W3R,W3I,P3r,P3i); \
    CMULW(O4r,O4i,W4R,W4I,P4r,P4i); \
    float b0r=E0r+O0r, b0i=E0i+O0i; \
    float b1r=E1r+P1r, b1i=E1i+P1i; \
    float b2r=E2r+P2r, b2i=E2i+P2i; \
    float b7r=E2r-P2r, b7i=E2i-P2i; \
    float b8r=E3r-P3r, b8i=E3i-P3i; \
    float b9r=E4r-P4r, b9i=E4i-P4i;

// deapodization inverse factor: 1/sinc^2((i-160)/640)
__device__ __forceinline__ float deapod_inv(int i)
{
    if (i == 160) return 1.0f;
    float px = 3.14159265358979324f * (float)(i - 160) * (1.0f/640.0f);
    float s = __sinf(px);
    float r = px / s;
    return r * r;
}

// ---------------- kernels ----------------
__global__ void k_zero_grid()
{
    unsigned i = blockIdx.x * blockDim.x + threadIdx.x;
    const unsigned n = (unsigned)(NFRAME*NCOIL) * GD * GD / 2;   // float4 count
    if (i < n) d_grid4[i] = make_float4(0.f,0.f,0.f,0.f);
}

__device__ __forceinline__ void red_v4(float* p, float a, float b, float c, float d)
{
    asm volatile("red.global.add.v4.f32 [%0], {%1, %2, %3, %4};"
                 :: "l"(p), "f"(a), "f"(b), "f"(c), "f"(d) : "memory");
}

__global__ void k_scatter(const float* __restrict__ ksr, const float* __restrict__ ksi,
                          const float* __restrict__ traj, const float* __restrict__ dcf)
{
    int idx = blockIdx.x * blockDim.x + threadIdx.x;   // t*MS + m
    if (idx >= NFRAME * MS) return;
    int t = idx >> 16;
    int m = idx & (MS - 1);

    float u = (traj[m*2*NFRAME + 0*NFRAME + t] + 0.5f) * (float)GD;
    float v = (traj[m*2*NFRAME + 1*NFRAME + t] + 0.5f) * (float)GD;
    float w = dcf[m*NFRAME + t];

    float u0f = floorf(u), v0f = floorf(v);
    float du = u - u0f, dv = v - v0f;
    int i0 = (int)u0f; if (i0 >= GD) i0 -= GD;
    int j0 = (int)v0f; if (j0 >= GD) j0 -= GD;
    int i1 = i0 + 1; if (i1 >= GD) i1 -= GD;
    int j1 = j0 + 1; if (j1 >= GD) j1 -= GD;

    float wc[4];
    wc[0] = (1.0f-du)*(1.0f-dv)*w;
    wc[1] = du*(1.0f-dv)*w;
    wc[2] = (1.0f-du)*dv*w;
    wc[3] = du*dv*w;
    size_t oc[4];
    oc[0] = ((size_t)i0*GD + j0) * NCOIL;
    oc[1] = ((size_t)i1*GD + j0) * NCOIL;
    oc[2] = ((size_t)i0*GD + j1) * NCOIL;
    oc[3] = ((size_t)i1*GD + j1) * NCOIL;

    float kr[NCOIL], ki[NCOIL];
    #pragma unroll
    for (int c = 0; c < NCOIL; c++) { kr[c] = ksr[c*MS + m]; ki[c] = ksi[c*MS + m]; }

    float* gbase = (float*)(d_grid4) + (size_t)t * GD * GD * NCOIL * 2;
    #pragma unroll
    for (int k = 0; k < 4; k++) {
        float* p = gbase + oc[k]*2;
        float ww = wc[k];
        #pragma unroll
        for (int h = 0; h < 4; h++) {
            red_v4(p + 4*h, kr[2*h]*ww, ki[2*h]*ww, kr[2*h+1]*ww, ki[2*h+1]*ww);
        }
    }
}

// Pass 1: block = (t, row r, coil-group cg of 4). 4 concurrent 640-pt FFTs
// along j. Stage 3 streams cropped+shifted rows directly to global.
__global__ void __launch_bounds__(320, 3) k_fft_pass1()
{
    __shared__ float cR[4][NP8], cI[4][NP8];   // input / stage2 dst
    __shared__ float pR[4][NP8], pI[4][NP8];   // ping
    int b = blockIdx.x;
    int cg = b & 1;
    int tr = b >> 1;
    int t  = tr / GD;
    int r  = tr - t * GD;
    int tid = threadIdx.x;

    // Coalesced (sector-aligned) load of 4 coils' row, with ifftshift on j.
    const float2* row = (const float2*)d_grid4 + ((size_t)(t*GD + r) * GD) * NCOIL + 4*cg;
    #pragma unroll
    for (int it = 0; it < 8; it++) {
        int idx = it * 320 + tid;
        int j  = idx >> 2;
        int cl = idx & 3;
        int jsh = (j < NXD) ? (j + NXD) : (j - NXD);
        float2 v = row[(size_t)j * NCOIL + cl];
        cR[cl][PADI8(jsh)] = v.x;  cI[cl][PADI8(jsh)] = v.y;
    }
    __syncthreads();

    int f  = tid / 80;
    int lt = tid - f * 80;

    s1_r8(cR[f], cI[f], pR[f], pI[f], lt);
    __syncthreads();
    s2_r8(pR[f], pI[f], cR[f], cI[f], lt);
    __syncthreads();

    // stage 3 + direct global write with fftshift+crop
    if (lt < 64) {
        const float* sr = cR[f];
        const float* si = cI[f];
        STAGE3_LOAD_AND_BFLY();
        int c = 4*cg + f;
        float2* orow = d_tmp1 + ((size_t)(t*NCOIL + c) * GD + r) * NXD;
        orow[lt+160] = make_float2(b0r, b0i);                 // k=0
        orow[lt+224] = make_float2(b1r, b1i);                 // k=1
        if (lt < 32)  orow[lt+288] = make_float2(b2r, b2i);   // k=2 (kk<160)
        if (lt >= 32) orow[lt-32]  = make_float2(b7r, b7i);   // k=7 (kk>=480)
        orow[lt+32]  = make_float2(b8r, b8i);                 // k=8
        orow[lt+96]  = make_float2(b9r, b9i);                 // k=9
    }
}

// Pass 2: block = (img, 4 columns). 4 concurrent FFTs along r. Stage 3 writes
// cropped+deapodized rows to ping; tile store coalesced.
__global__ void __launch_bounds__(320, 3) k_fft_pass2()
{
    __shared__ float cR[4][NP8], cI[4][NP8];
    __shared__ float pR[4][NP8], pI[4][NP8];
    int img = blockIdx.x / (NXD/4);
    int jb  = (blockIdx.x - img * (NXD/4)) * 4;
    int tid = threadIdx.x;

    const float2* base = d_tmp1 + (size_t)img * GD * NXD + jb;
    #pragma unroll
    for (int it = 0; it < 8; it++) {
        int idx = it * 320 + tid;
        int rr = idx >> 2;
        int cl = idx & 3;
        int rsh = (rr < NXD) ? (rr + NXD) : (rr - NXD);
        float2 v = base[(size_t)rr * NXD + cl];
        cR[cl][PADI8(rsh)] = v.x;  cI[cl][PADI8(rsh)] = v.y;
    }
    __syncthreads();

    int f  = tid / 80;
    int lt = tid - f * 80;

    s1_r8(cR[f], cI[f], pR[f], pI[f], lt);
    __syncthreads();
    s2_r8(pR[f], pI[f], cR[f], cI[f], lt);
    __syncthreads();

    if (lt < 64) {
        const float* sr = cR[f];
        const float* si = cI[f];
        STAGE3_LOAD_AND_BFLY();
        int j = jb + f;
        float sj = (1.0f/409600.0f) * deapod_inv(j);
        float* qr = pR[f];
        float* qi = pI[f];
        int i;
        i = lt+160; { float s = sj*deapod_inv(i); qr[PADI8(i)] = b0r*s; qi[PADI8(i)] = b0i*s; }
        i = lt+224; { float s = sj*deapod_inv(i); qr[PADI8(i)] = b1r*s; qi[PADI8(i)] = b1i*s; }
        if (lt < 32)  { i = lt+288; float s = sj*deapod_inv(i); qr[PADI8(i)] = b2r*s; qi[PADI8(i)] = b2i*s; }
        if (lt >= 32) { i = lt-32;  float s = sj*deapod_inv(i); qr[PADI8(i)] = b7r*s; qi[PADI8(i)] = b7i*s; }
        i = lt+32;  { float s = sj*deapod_inv(i); qr[PADI8(i)] = b8r*s; qi[PADI8(i)] = b8i*s; }
        i = lt+96;  { float s = sj*deapod_inv(i); qr[PADI8(i)] = b9r*s; qi[PADI8(i)] = b9i*s; }
    }
    __syncthreads();

    float2* obase = d_imcrop + (size_t)img * NPIX + jb;
    #pragma unroll
    for (int it = 0; it < 4; it++) {
        int idx = it * 320 + tid;
        int i  = idx >> 2;
        int cl = idx & 3;
        obase[(size_t)i * NXD + cl] = make_float2(pR[cl][PADI8(i)], pI[cl][PADI8(i)]);
    }
}

// Coil combine: imt[t][pix] = sum_c conj(csm[c]) * im[t][c]
__global__ void k_combine(const float* __restrict__ csr, const float* __restrict__ csi)
{
    int idx = blockIdx.x * blockDim.x + threadIdx.x;   // t*NPIX + pix
    if (idx >= NFRAME * NPIX) return;
    int t = idx / NPIX;
    int pix = idx - t * NPIX;
    float re = 0.f, im = 0.f;
    #pragma unroll
    for (int c = 0; c < NCOIL; c++) {
        float2 v = d_imcrop[(size_t)(t*NCOIL + c) * NPIX + pix];
        float cr = csr[c*NPIX + pix];
        float ci = csi[c*NPIX + pix];
        re += cr*v.x + ci*v.y;
        im += cr*v.y - ci*v.x;
    }
    d_imt[idx] = make_float2(re, im);
}

// Motion warp each frame and sum over frames.
__global__ void k_warp_sum(const float* __restrict__ motions, float* __restrict__ out)
{
    int idx = blockIdx.x * blockDim.x + threadIdx.x;   // x*NXD + y
    if (idx >= NPIX) return;
    int x = idx / NXD;
    int y = idx - x * NXD;

    float accr = 0.f, acci = 0.f;
    #pragma unroll
    for (int t = 0; t < NFRAME; t++) {
        float fx = (float)x + motions[(idx*2 + 0)*NFRAME + t];
        float fy = (float)y + motions[(idx*2 + 1)*NFRAME + t];
        fx = fminf(fmaxf(fx, 0.0f), (float)(NXD-1));
        fy = fminf(fmaxf(fy, 0.0f), (float)(NXD-1));
        int x0 = (int)floorf(fx);
        int y0 = (int)floorf(fy);
        int x1 = min(x0 + 1, NXD-1);
        int y1 = min(y0 + 1, NXD-1);
        float dx = fx - (float)x0;
        float dy = fy - (float)y0;
        const float2* im = d_imt + (size_t)t * NPIX;
        float2 v00 = im[x0*NXD + y0];
        float2 v10 = im[x1*NXD + y0];
        float2 v01 = im[x0*NXD + y1];
        float2 v11 = im[x1*NXD + y1];
        float w00 = (1.f-dx)*(1.f-dy), w10 = dx*(1.f-dy), w01 = (1.f-dx)*dy, w11 = dx*dy;
        accr += w00*v00.x + w10*v10.x + w01*v01.x + w11*v11.x;
        acci += w00*v00.y + w10*v10.y + w01*v01.y + w11*v11.y;
    }
    out[idx*2 + 0] = accr;
    out[idx*2 + 1] = acci;
}

// ---------------- launch ----------------
extern "C" void kernel_launch(void* const* d_in, const int* in_sizes, int n_in,
                              void* d_out, int out_size)
{
    const float* ksr     = (const float*)d_in[0];
    const float* ksi     = (const float*)d_in[1];
    const float* traj    = (const float*)d_in[2];
    const float* csr     = (const float*)d_in[3];
    const float* csi     = (const float*)d_in[4];
    const float* dcf     = (const float*)d_in[5];
    const float* motions = (const float*)d_in[6];
    float* out = (float*)d_out;

    const int nzero = NFRAME*NCOIL*GD*GD/2;                 // float4 elements
    k_zero_grid<<<(nzero + 255)/256, 256>>>();
    k_scatter<<<(NFRAME*MS + 255)/256, 256>>>(ksr, ksi, traj, dcf);
    k_fft_pass1<<<NFRAME*GD*2, 320>>>();
    k_fft_pass2<<<NFRAME*NCOIL*(NXD/4), 320>>>();
    k_combine<<<(NFRAME*NPIX + 255)/256, 256>>>(csr, csi);
    k_warp_sum<<<(NPIX + 255)/256, 256>>>(motions, out);
}